// round 14
// baseline (speedup 1.0000x reference)
#include <cuda_runtime.h>

#define M_SZ    100
#define H_SZ    256
#define W_SZ    512
#define N_INST  64
#define C_THING 80
#define C_STUFF 53
#define C_OUT   (C_STUFF + N_INST)   // 117
#define WARPS_PB 8
#define STREAM_BLOCKS (C_OUT * H_SZ / WARPS_PB)  // 3744 (launch first)
#define BOX_BLOCKS N_INST                         // 64, at the tail

// Single launch, element-disjoint writes:
//  - stream blocks (blockIdx < STREAM_BLOCKS): stuff-row copies; thing rows
//    zeroed except the in-box columns [x1b, xend).
//  - box blocks (last 64, one per instance): 8 warps, each loops rows
//    y1b + w + 8k; one float4-quad per lane inside [x1b, xend).
__global__ __launch_bounds__(256)
void panoptic_fused_kernel(const float* __restrict__ mask_logits,   // [N,80,M,M]
                           const float* __restrict__ sem_seg,       // [1,133,H,W]
                           const float* __restrict__ bbox,          // [N,4]
                           const int*   __restrict__ cls_idx,       // [N]
                           float* __restrict__ out)                 // [1,117,H,W]
{
    const int tid  = threadIdx.x;
    const int lane = tid & 31;

    if (blockIdx.x < STREAM_BLOCKS) {
        // ================= streaming part =================
        const int warp = tid >> 5;
        const int grow = blockIdx.x * WARPS_PB + warp;
        const int c    = grow >> 8;                     // H == 256
        float4* __restrict__ orow = (float4*)(out + (size_t)grow * W_SZ);

        if (c < C_STUFF) {
            const float4* __restrict__ srow =
                (const float4*)(sem_seg + (size_t)grow * W_SZ);
            float4 v0 = srow[lane];
            float4 v1 = srow[lane + 32];
            float4 v2 = srow[lane + 64];
            float4 v3 = srow[lane + 96];
            orow[lane]      = v0;
            orow[lane + 32] = v1;
            orow[lane + 64] = v2;
            orow[lane + 96] = v3;
            return;
        }

        const int n = c - C_STUFF;
        const int y = grow & (H_SZ - 1);

        const float bx1 = __ldg(&bbox[n * 4 + 0]);
        const float by1 = __ldg(&bbox[n * 4 + 1]);
        const float bx2 = __ldg(&bbox[n * 4 + 2]);
        const float by2 = __ldg(&bbox[n * 4 + 3]);

        const int x1b  = (int)floorf(bx1);
        const int y1b  = (int)floorf(by1);
        const int cy2  = (int)rintf(by2) + 1;
        const int cx2  = (int)rintf(bx2) + 1;
        const int rend = min(cy2, H_SZ);     // row union end
        const int xend = min(cx2, W_SZ);     // col union end

        const float4 z = make_float4(0.f, 0.f, 0.f, 0.f);
        const bool row_in_union = (y >= y1b) && (y < rend);

        if (!row_in_union) {
            orow[lane]      = z;
            orow[lane + 32] = z;
            orow[lane + 64] = z;
            orow[lane + 96] = z;
            return;
        }

        // zero only columns outside [x1b, xend); box block owns the inside
        float* __restrict__ orowf = (float*)orow;
        #pragma unroll
        for (int j = 0; j < 4; ++j) {
            const int idx   = lane + 32 * j;
            const int xbase = idx * 4;
            if (xbase + 3 < x1b || xbase >= xend) {
                orow[idx] = z;                       // fully outside: vector zero
            } else if (xbase >= x1b && xbase + 3 < xend) {
                // fully inside: box block writes it
            } else {
                #pragma unroll
                for (int e = 0; e < 4; ++e) {
                    const int x = xbase + e;
                    if (x < x1b || x >= xend) orowf[x] = 0.f;
                }
            }
        }
        return;
    }

    // ================= box part: one block per instance =================
    const int n = blockIdx.x - STREAM_BLOCKS;
    const int w = tid >> 5;

    const float bx1 = __ldg(&bbox[n * 4 + 0]);
    const float by1 = __ldg(&bbox[n * 4 + 1]);
    const float bx2 = __ldg(&bbox[n * 4 + 2]);
    const float by2 = __ldg(&bbox[n * 4 + 3]);
    const int   cls = __ldg(&cls_idx[n]);

    const int x1b = (int)floorf(bx1);
    const int y1b = (int)floorf(by1);
    const int x2b = (int)floorf(bx2);
    const int y2b = (int)floorf(by2);
    const int cy2 = (int)rintf(by2) + 1;
    const int cx2 = (int)rintf(bx2) + 1;

    const int rend = min(cy2, H_SZ);
    const int xend = min(cx2, W_SZ);
    const int pyhi = min(y2b + 1, H_SZ);
    const int xhi  = min(x2b + 1, W_SZ);
    const float invbw = (float)M_SZ / (float)(x2b - x1b + 1);
    const float invbh = (float)M_SZ / (float)(y2b - y1b + 1);

    const float* __restrict__ mtile =
        mask_logits + ((size_t)n * C_THING + (size_t)cls) * (M_SZ * M_SZ);
    const float* __restrict__ schan =
        sem_seg + (size_t)(C_STUFF + cls) * H_SZ * W_SZ;
    float* __restrict__ ochan =
        out + (size_t)(C_STUFF + n) * H_SZ * W_SZ;

    // quad assignment for this lane (constant across rows)
    const int qlo = x1b >> 2;
    const int qhi = (xend + 3) >> 2;            // exclusive
    const int q   = qlo + lane;
    const bool lane_active = (q < qhi);
    const int  xb   = q * 4;
    const bool full = lane_active && (xb >= x1b) && (xb + 3 < xend);

    for (int y = y1b + w; y < rend; y += 8) {
        const bool in_paste = (y < pyhi);
        const bool in_crop  = (y < cy2);        // true while y < rend <= cy2

        float v[4] = {0.f, 0.f, 0.f, 0.f};

        if (lane_active && in_paste) {
            float my = ((float)y - (float)y1b + 0.5f) * invbh - 0.5f;
            my = fmaxf(my, 0.f);
            const float myf = floorf(my);
            const float fy  = my - myf;
            const int iy0 = min((int)myf,     M_SZ - 1);
            const int iy1 = min((int)myf + 1, M_SZ - 1);
            const float* __restrict__ mrow0 = mtile + iy0 * M_SZ;
            const float* __restrict__ mrow1 = mtile + iy1 * M_SZ;
            #pragma unroll
            for (int e = 0; e < 4; ++e) {
                const int x = xb + e;
                if (x >= x1b && x < xhi) {
                    float mx = ((float)x - (float)x1b + 0.5f) * invbw - 0.5f;
                    mx = fmaxf(mx, 0.f);
                    const float mxf = floorf(mx);
                    const float fx  = mx - mxf;
                    const int ix0 = min((int)mxf,     M_SZ - 1);
                    const int ix1 = min((int)mxf + 1, M_SZ - 1);
                    const float top = mrow0[ix0] * (1.f - fx) + mrow0[ix1] * fx;
                    const float bot = mrow1[ix0] * (1.f - fx) + mrow1[ix1] * fx;
                    v[e] = (1.f - fy) * top + fy * bot;
                }
            }
        }

        if (lane_active && in_crop) {
            const float* __restrict__ srow = schan + (size_t)y * W_SZ;
            if (full) {
                const float4 s = *(const float4*)(srow + xb);
                v[0] += s.x; v[1] += s.y; v[2] += s.z; v[3] += s.w;
            } else {
                #pragma unroll
                for (int e = 0; e < 4; ++e) {
                    const int x = xb + e;
                    if (x >= x1b && x < xend) v[e] += __ldg(&srow[x]);
                }
            }
        }

        if (lane_active) {
            float* __restrict__ orow = ochan + (size_t)y * W_SZ;
            if (full) {
                *(float4*)(orow + xb) = make_float4(v[0], v[1], v[2], v[3]);
            } else {
                #pragma unroll
                for (int e = 0; e < 4; ++e) {
                    const int x = xb + e;
                    if (x >= x1b && x < xend) orow[x] = v[e];
                }
            }
        }
    }
}

extern "C" void kernel_launch(void* const* d_in, const int* in_sizes, int n_in,
                              void* d_out, int out_size)
{
    const float* mask_logits = (const float*)d_in[0];
    const float* sem_seg     = (const float*)d_in[1];
    const float* bbox        = (const float*)d_in[2];
    const int*   cls_idx     = (const int*)d_in[3];
    float*       out         = (float*)d_out;

    panoptic_fused_kernel<<<STREAM_BLOCKS + BOX_BLOCKS, 256>>>(
        mask_logits, sem_seg, bbox, cls_idx, out);
}

// round 15
// speedup vs baseline: 1.9193x; 1.9193x over previous
#include <cuda_runtime.h>

#define M_SZ    100
#define H_SZ    256
#define W_SZ    512
#define N_INST  64
#define C_THING 80
#define C_STUFF 53
#define C_OUT   (C_STUFF + N_INST)   // 117
#define WARPS_PB 8
#define BOX_BLOCKS (N_INST * 10)     // 640: 10 row-groups x 64 instances
#define STREAM_BLOCKS (C_OUT * H_SZ / WARPS_PB)  // 3744

// Single launch, element-disjoint writes:
//  - box blocks (first 640): columns inside [x1b, xend) of box-union rows.
//    Fully predicated column loop -> all 3 chunks' loads issue in parallel.
//  - stream blocks: stuff-row copies; thing rows zeroed except in-box columns.
__global__ __launch_bounds__(256, 8)
void panoptic_fused_kernel(const float* __restrict__ mask_logits,   // [N,80,M,M]
                           const float4* __restrict__ bbox4,        // [N]
                           const float* __restrict__ sem_seg,       // [1,133,H,W]
                           const int*   __restrict__ cls_idx,       // [N]
                           float* __restrict__ out)                 // [1,117,H,W]
{
    const int tid  = threadIdx.x;
    const int lane = tid & 31;

    if (blockIdx.x >= BOX_BLOCKS) {
        // ================= streaming part =================
        const int warp = tid >> 5;
        const int grow = (blockIdx.x - BOX_BLOCKS) * WARPS_PB + warp;
        const int c    = grow >> 8;                     // H == 256
        float4* __restrict__ orow = (float4*)(out + (size_t)grow * W_SZ);

        if (c < C_STUFF) {
            const float4* __restrict__ srow =
                (const float4*)(sem_seg + (size_t)grow * W_SZ);
            float4 v0 = srow[lane];
            float4 v1 = srow[lane + 32];
            float4 v2 = srow[lane + 64];
            float4 v3 = srow[lane + 96];
            orow[lane]      = v0;
            orow[lane + 32] = v1;
            orow[lane + 64] = v2;
            orow[lane + 96] = v3;
            return;
        }

        const int n = c - C_STUFF;
        const int y = grow & (H_SZ - 1);

        const float4 bb = __ldg(&bbox4[n]);

        const int x1b  = (int)floorf(bb.x);
        const int y1b  = (int)floorf(bb.y);
        const int cy2  = (int)rintf(bb.w) + 1;
        const int cx2  = (int)rintf(bb.z) + 1;
        const int rend = min(cy2, H_SZ);     // row union end
        const int xend = min(cx2, W_SZ);     // col union end

        const float4 z = make_float4(0.f, 0.f, 0.f, 0.f);
        const bool row_in_union = (y >= y1b) && (y < rend);

        if (!row_in_union) {
            orow[lane]      = z;
            orow[lane + 32] = z;
            orow[lane + 64] = z;
            orow[lane + 96] = z;
            return;
        }

        // zero only columns outside [x1b, xend); box block owns the inside
        float* __restrict__ orowf = (float*)orow;
        #pragma unroll
        for (int j = 0; j < 4; ++j) {
            const int idx   = lane + 32 * j;
            const int xbase = idx * 4;
            if (xbase + 3 < x1b || xbase >= xend) {
                orow[idx] = z;                       // fully outside: vector zero
            } else if (xbase >= x1b && xbase + 3 < xend) {
                // fully inside: box block writes it
            } else {
                #pragma unroll
                for (int e = 0; e < 4; ++e) {
                    const int x = xbase + e;
                    if (x < x1b || x >= xend) orowf[x] = 0.f;
                }
            }
        }
        return;
    }

    // ================= box part =================
    const int bb_i = blockIdx.x;
    const int n    = bb_i & (N_INST - 1);           // 64 instances
    const int rg   = bb_i >> 6;                      // 10 row groups

    const float4 bb = __ldg(&bbox4[n]);
    const int   cls = __ldg(&cls_idx[n]);

    const int x1b = (int)floorf(bb.x);
    const int y1b = (int)floorf(bb.y);
    const int x2b = (int)floorf(bb.z);
    const int y2b = (int)floorf(bb.w);
    const int cy2 = (int)rintf(bb.w) + 1;
    const int cx2 = (int)rintf(bb.z) + 1;

    const int rend = min(cy2, H_SZ);
    const int xend = min(cx2, W_SZ);

    const int y = y1b + rg * 8 + (tid >> 5);
    if (y >= rend) return;

    const int  pyhi     = min(y2b + 1, H_SZ);
    const bool in_paste = (y < pyhi);               // y >= y1b by construction
    const bool in_crop  = (y < cy2);

    const float* __restrict__ mrow0 = nullptr;
    const float* __restrict__ mrow1 = nullptr;
    float fy = 0.f;
    const int xhi = min(x2b + 1, W_SZ);
    const float invbw = (float)M_SZ / (float)(x2b - x1b + 1);

    if (in_paste) {
        const float* __restrict__ mtile =
            mask_logits + ((size_t)n * C_THING + (size_t)cls) * (M_SZ * M_SZ);
        float my = ((float)y - (float)y1b + 0.5f) *
                   ((float)M_SZ / (float)(y2b - y1b + 1)) - 0.5f;
        my = fmaxf(my, 0.f);
        const float myf = floorf(my);
        fy = my - myf;
        const int iy0 = min((int)myf,     M_SZ - 1);
        const int iy1 = min((int)myf + 1, M_SZ - 1);
        mrow0 = mtile + iy0 * M_SZ;
        mrow1 = mtile + iy1 * M_SZ;
    }

    const float* __restrict__ srow =
        sem_seg + ((size_t)(C_STUFF + cls) * H_SZ + (size_t)y) * W_SZ;
    float* __restrict__ orow =
        out + ((size_t)(C_STUFF + n) * H_SZ + (size_t)y) * W_SZ;

    // fully predicated: all 3 chunks' loads can issue back-to-back
    float m00[3], m01[3], m10[3], m11[3], sv[3], fxv[3];
    bool  act[3], pst[3], crp[3];
    int   xs[3];

    #pragma unroll
    for (int k = 0; k < 3; ++k) {
        const int x = x1b + lane + 32 * k;
        xs[k]  = x;
        act[k] = (x < xend);
        pst[k] = in_paste && (x < xhi);
        crp[k] = in_crop && act[k];

        float mx = ((float)x - (float)x1b + 0.5f) * invbw - 0.5f;
        mx = fmaxf(mx, 0.f);
        const float mxf = floorf(mx);
        fxv[k] = mx - mxf;
        const int ix0 = min((int)mxf,     M_SZ - 1);
        const int ix1 = min((int)mxf + 1, M_SZ - 1);

        m00[k] = pst[k] ? __ldg(&mrow0[ix0]) : 0.f;
        m01[k] = pst[k] ? __ldg(&mrow0[ix1]) : 0.f;
        m10[k] = pst[k] ? __ldg(&mrow1[ix0]) : 0.f;
        m11[k] = pst[k] ? __ldg(&mrow1[ix1]) : 0.f;
        sv[k]  = crp[k] ? __ldg(&srow[x])    : 0.f;
    }

    #pragma unroll
    for (int k = 0; k < 3; ++k) {
        if (!act[k]) continue;
        float val = sv[k];
        if (pst[k]) {
            const float fx  = fxv[k];
            const float top = m00[k] * (1.f - fx) + m01[k] * fx;
            const float bot = m10[k] * (1.f - fx) + m11[k] * fx;
            val += (1.f - fy) * top + fy * bot;
        }
        orow[xs[k]] = val;
    }
}

extern "C" void kernel_launch(void* const* d_in, const int* in_sizes, int n_in,
                              void* d_out, int out_size)
{
    const float*  mask_logits = (const float*)d_in[0];
    const float*  sem_seg     = (const float*)d_in[1];
    const float4* bbox4       = (const float4*)d_in[2];
    const int*    cls_idx     = (const int*)d_in[3];
    float*        out         = (float*)d_out;

    panoptic_fused_kernel<<<BOX_BLOCKS + STREAM_BLOCKS, 256>>>(
        mask_logits, bbox4, sem_seg, cls_idx, out);
}